// round 2
// baseline (speedup 1.0000x reference)
#include <cuda_runtime.h>
#include <cuda_bf16.h>
#include <math.h>
#include <stdint.h>

#define NBANDS 160
#define NROWS  96
#define TLEN   2048
#define HALF_T 1024
#define NTRIL  4560   // 96*95/2
#define SORTN  8192

// ---------------- scratch (static device globals; no allocation) ----------------
__device__ float  g_xc[(size_t)NBANDS * NROWS * TLEN];    // centered rows (fp32, unnormalized)
__device__ double g_norm2[(size_t)NBANDS * NROWS];        // ||Xc||^2 in fp64
__device__ float  g_C[(size_t)NBANDS * NROWS * NROWS];    // correlation matrices (fp32, correctly rounded)
__device__ float  g_feat[(size_t)NBANDS * 5 * NROWS];     // per-row 5 features
__device__ float  g_thr[NBANDS];

// ---------------- reductions ----------------
__device__ __forceinline__ float blockReduceSum(float val, float* red) {
    __syncthreads();
    int lane = threadIdx.x & 31, wid = threadIdx.x >> 5;
    #pragma unroll
    for (int o = 16; o > 0; o >>= 1) val += __shfl_xor_sync(0xffffffffu, val, o);
    if (lane == 0) red[wid] = val;
    __syncthreads();
    if (wid == 0) {
        int nw = (blockDim.x + 31) >> 5;
        float v = (lane < nw) ? red[lane] : 0.f;
        #pragma unroll
        for (int o = 16; o > 0; o >>= 1) v += __shfl_xor_sync(0xffffffffu, v, o);
        if (lane == 0) red[0] = v;
    }
    __syncthreads();
    return red[0];
}

__device__ __forceinline__ double blockReduceSumD(double val, double* redd) {
    __syncthreads();
    int lane = threadIdx.x & 31, wid = threadIdx.x >> 5;
    #pragma unroll
    for (int o = 16; o > 0; o >>= 1) val += __shfl_xor_sync(0xffffffffu, val, o);
    if (lane == 0) redd[wid] = val;
    __syncthreads();
    if (wid == 0) {
        int nw = (blockDim.x + 31) >> 5;
        double v = (lane < nw) ? redd[lane] : 0.0;
        #pragma unroll
        for (int o = 16; o > 0; o >>= 1) v += __shfl_xor_sync(0xffffffffu, v, o);
        if (lane == 0) redd[0] = v;
    }
    __syncthreads();
    return redd[0];
}

__device__ __forceinline__ float blockReduceMax(float val, float* red) {
    __syncthreads();
    int lane = threadIdx.x & 31, wid = threadIdx.x >> 5;
    #pragma unroll
    for (int o = 16; o > 0; o >>= 1) val = fmaxf(val, __shfl_xor_sync(0xffffffffu, val, o));
    if (lane == 0) red[wid] = val;
    __syncthreads();
    if (wid == 0) {
        int nw = (blockDim.x + 31) >> 5;
        float v = (lane < nw) ? red[lane] : -INFINITY;
        #pragma unroll
        for (int o = 16; o > 0; o >>= 1) v = fmaxf(v, __shfl_xor_sync(0xffffffffu, v, o));
        if (lane == 0) red[0] = v;
    }
    __syncthreads();
    return red[0];
}

// ---------------- kernel 1: per-row stats + center (fp64 mean) + FFT entropy ----------------
// grid (96, 160), block 256
__global__ void stats_fft_kernel(const float* __restrict__ wc) {
    const int row = blockIdx.x;
    const int band = blockIdx.y;
    const int b = band / 5, nb = band % 5;
    const float* __restrict__ x = wc + (((size_t)b * NROWS + row) * 5 + nb) * TLEN;

    __shared__ float re[TLEN];
    __shared__ float im[TLEN];
    __shared__ float twr[HALF_T];
    __shared__ float twi[HALF_T];
    __shared__ float red[32];
    __shared__ double redd[32];

    const int tid = threadIdx.x;

    float v[8];
    double s = 0.0, sq = 0.0;
    float mx = 0.f;
    #pragma unroll
    for (int k = 0; k < 8; k++) {
        float t = x[tid + 256 * k];
        v[k] = t;
        s += (double)t; sq += (double)t * (double)t; mx = fmaxf(mx, fabsf(t));
    }

    // twiddles: tw[k] = exp(-2*pi*i*k/2048)
    for (int k = tid; k < HALF_T; k += 256) {
        float sv, cv;
        sincospif(-(float)k / 1024.0f, &sv, &cv);
        twr[k] = cv; twi[k] = sv;
    }
    // bit-reversed load of original x (FFT is on un-centered X)
    #pragma unroll
    for (int k = 0; k < 8; k++) {
        int idx = tid + 256 * k;
        int r = __brev((unsigned)idx) >> 21;  // 11-bit reverse
        re[r] = v[k];
        im[r] = 0.f;
    }

    double ssum   = blockReduceSumD(s, redd);
    double energy = blockReduceSumD(sq, redd);
    float  maxamp = blockReduceMax(mx, red);
    float  meanf  = (float)(ssum / (double)TLEN);

    // centered rows in fp32 (matches reference's fp32 Xc), norm^2 in fp64
    float cx[8];
    double csq = 0.0;
    #pragma unroll
    for (int k = 0; k < 8; k++) {
        cx[k] = v[k] - meanf;
        csq += (double)cx[k] * (double)cx[k];
    }
    double norm2 = blockReduceSumD(csq, redd);
    float stdf = (float)sqrt(norm2 / (double)(TLEN - 1));

    float* __restrict__ xc = g_xc + ((size_t)band * NROWS + row) * TLEN;
    #pragma unroll
    for (int k = 0; k < 8; k++) xc[tid + 256 * k] = cx[k];
    if (tid == 0) g_norm2[(size_t)band * NROWS + row] = norm2;

    // FFT (DIT radix-2, bit-reversed input, natural output)
    #pragma unroll 1
    for (int st = 1; st <= 11; st++) {
        const int half = 1 << (st - 1);
        __syncthreads();
        #pragma unroll 1
        for (int bfly = tid; bfly < HALF_T; bfly += 256) {
            int j = bfly & (half - 1);
            int grp = bfly >> (st - 1);
            int p0 = (grp << st) + j;
            int p1 = p0 + half;
            int ti = j << (11 - st);
            float wr = twr[ti], wi = twi[ti];
            float r1 = re[p1], i1 = im[p1];
            float vr = r1 * wr - i1 * wi;
            float vi = r1 * wi + i1 * wr;
            float ur = re[p0], ui = im[p0];
            re[p0] = ur + vr; im[p0] = ui + vi;
            re[p1] = ur - vr; im[p1] = ui - vi;
        }
    }
    __syncthreads();

    double psum = 0.0;
    for (int k = tid; k < HALF_T; k += 256) {
        float ps = re[k] * re[k] + im[k] * im[k];
        psum += (double)ps;
    }
    double S = blockReduceSumD(psum, redd);
    double Sd = (S == 0.0) ? 1.0 : S;
    double entp = 0.0;
    for (int k = tid; k < HALF_T; k += 256) {
        float ps = re[k] * re[k] + im[k] * im[k];
        float p = (float)((double)ps / Sd);
        entp += (double)(p * logf(p + 1e-10f));
    }
    double ent = -blockReduceSumD(entp, redd);

    if (tid == 0) {
        float* f = g_feat + (size_t)band * 5 * NROWS;
        f[0 * NROWS + row] = meanf;
        f[1 * NROWS + row] = stdf;
        f[2 * NROWS + row] = (float)energy;
        f[3 * NROWS + row] = maxamp;
        f[4 * NROWS + row] = (float)ent;
    }
}

// ---------------- kernel 2: correlation GEMM C = Xc @ Xc^T / (norm norm^T) per band ----------------
// grid (2, 160): each block does 48 rows x 96 cols. block 256 (16x16), thread tile 3x6.
// fp32 FMA inner loops over K-chunks of 64; chunk sums accumulated into fp64.
__global__ void corr_kernel() {
    const int band = blockIdx.y;
    const int half = blockIdx.x;          // 0 or 1 (rows 0-47 / 48-95)
    __shared__ float st[64][97];          // transposed tile: st[k][row]
    __shared__ double n2s[NROWS];
    const float* __restrict__ Xb = g_xc + (size_t)band * NROWS * TLEN;

    const int tid = threadIdx.x;
    const int tx = tid & 15, ty = tid >> 4;

    if (tid < NROWS) n2s[tid] = g_norm2[(size_t)band * NROWS + tid];

    double accd[3][6];
    #pragma unroll
    for (int u = 0; u < 3; u++)
        #pragma unroll
        for (int w = 0; w < 6; w++) accd[u][w] = 0.0;

    const int rbase = half * 48;

    for (int kt = 0; kt < TLEN; kt += 64) {
        // load 96 rows x 64 k, transposed into smem
        #pragma unroll
        for (int i = tid; i < 1536; i += 256) {
            int r = i >> 4, q = i & 15;
            float4 g = *reinterpret_cast<const float4*>(Xb + (size_t)r * TLEN + kt + q * 4);
            st[q * 4 + 0][r] = g.x;
            st[q * 4 + 1][r] = g.y;
            st[q * 4 + 2][r] = g.z;
            st[q * 4 + 3][r] = g.w;
        }
        __syncthreads();

        float acc[3][6];
        #pragma unroll
        for (int u = 0; u < 3; u++)
            #pragma unroll
            for (int w = 0; w < 6; w++) acc[u][w] = 0.f;

        #pragma unroll 4
        for (int k = 0; k < 64; k++) {
            float a[3], bb[6];
            #pragma unroll
            for (int u = 0; u < 3; u++) a[u]  = st[k][rbase + ty + 16 * u];
            #pragma unroll
            for (int w = 0; w < 6; w++) bb[w] = st[k][tx + 16 * w];
            #pragma unroll
            for (int u = 0; u < 3; u++)
                #pragma unroll
                for (int w = 0; w < 6; w++)
                    acc[u][w] = fmaf(a[u], bb[w], acc[u][w]);
        }
        __syncthreads();

        #pragma unroll
        for (int u = 0; u < 3; u++)
            #pragma unroll
            for (int w = 0; w < 6; w++) accd[u][w] += (double)acc[u][w];
    }

    float* __restrict__ Cb = g_C + (size_t)band * NROWS * NROWS;
    #pragma unroll
    for (int u = 0; u < 3; u++) {
        int r = rbase + ty + 16 * u;
        double ni = sqrt(n2s[r]);
        if (ni == 0.0) ni = 1.0;
        #pragma unroll
        for (int w = 0; w < 6; w++) {
            int c = tx + 16 * w;
            double nj = sqrt(n2s[c]);
            if (nj == 0.0) nj = 1.0;
            double val = accd[u][w] / (ni * nj);
            Cb[r * NROWS + c] = (r == c) ? 0.f : (float)val;
        }
    }
}

// ---------------- kernel 3: exact quantile via bitonic sort ----------------
// grid 160, block 1024
__global__ void quantile_kernel() {
    __shared__ float s[SORTN];
    const int band = blockIdx.x;
    const int tid = threadIdx.x;
    const float* __restrict__ Cb = g_C + (size_t)band * NROWS * NROWS;

    for (int i = tid; i < SORTN; i += 1024) s[i] = INFINITY;
    __syncthreads();
    for (int idx = tid; idx < NROWS * NROWS; idx += 1024) {
        int i = idx / NROWS, j = idx - i * NROWS;
        if (j < i) s[i * (i - 1) / 2 + j] = fabsf(Cb[idx]);
    }

    for (int k = 2; k <= SORTN; k <<= 1) {
        for (int j = k >> 1; j > 0; j >>= 1) {
            __syncthreads();
            #pragma unroll 1
            for (int i = tid; i < SORTN; i += 1024) {
                int ixj = i ^ j;
                if (ixj > i) {
                    float a = s[i], b = s[ixj];
                    bool up = ((i & k) == 0);
                    if ((a > b) == up) { s[i] = b; s[ixj] = a; }
                }
            }
        }
    }
    __syncthreads();
    if (tid == 0) {
        // q = 0.8, N = 4560 -> pos = 0.8*(N-1) = 3647.2
        double pos = 0.8 * (double)(NTRIL - 1);
        int lo = (int)pos;
        double fr = pos - (double)lo;
        g_thr[band] = (float)((double)s[lo] + fr * ((double)s[lo + 1] - (double)s[lo]));
    }
}

// ---------------- kernel 4: mask + graph props + MLP ----------------
// grid 160, block 128
__global__ void finalize_kernel(const int* __restrict__ community,
                                const float* __restrict__ W1, const float* __restrict__ b1,
                                const float* __restrict__ W2, const float* __restrict__ b2,
                                float* __restrict__ outA, float* __restrict__ outF) {
    const int band = blockIdx.x;
    const int tid = threadIdx.x;

    __shared__ unsigned bits[NROWS][3];
    __shared__ float degf[NROWS];
    __shared__ int comm[NROWS];
    __shared__ float red[32];
    __shared__ float feat11[11];
    __shared__ float h[32];
    __shared__ float sprops[6];

    const float thr = g_thr[band];
    const float* __restrict__ Cb = g_C + (size_t)band * NROWS * NROWS;
    float* __restrict__ Ao = outA + (size_t)band * NROWS * NROWS;

    if (tid < NROWS) comm[tid] = community[tid];

    int mydeg = 0;
    if (tid < NROWS) {
        unsigned b0 = 0, b1w = 0, b2w = 0;
        const float* crow = Cb + tid * NROWS;
        float* arow = Ao + tid * NROWS;
        #pragma unroll 4
        for (int j = 0; j < NROWS; j++) {
            float c = crow[j];
            bool keep = (fabsf(c) >= thr) && (j != tid);
            arow[j] = keep ? c : 0.f;
            if (keep) {
                mydeg++;
                if (j < 32) b0 |= 1u << j;
                else if (j < 64) b1w |= 1u << (j - 32);
                else b2w |= 1u << (j - 64);
            }
        }
        bits[tid][0] = b0; bits[tid][1] = b1w; bits[tid][2] = b2w;
        degf[tid] = (float)mydeg;
    }
    __syncthreads();

    float degsum = blockReduceSum(tid < NROWS ? (float)mydeg : 0.f, red);
    float ne = 0.5f * degsum;

    // triangles: sum over ordered (i,j) edges of |N(i) ∩ N(j)| = 6*tri
    float cnt = 0.f;
    if (tid < NROWS) {
        unsigned r0 = bits[tid][0], r1 = bits[tid][1], r2 = bits[tid][2];
        int c6 = 0;
        #pragma unroll 1
        for (int w = 0; w < 3; w++) {
            unsigned mw = bits[tid][w];
            while (mw) {
                int j = __ffs(mw) - 1 + 32 * w;
                mw &= mw - 1;
                c6 += __popc(r0 & bits[j][0]) + __popc(r1 & bits[j][1]) + __popc(r2 & bits[j][2]);
            }
        }
        cnt = (float)c6;
    }
    float tri6 = blockReduceSum(cnt, red);
    float tri = tri6 / 6.0f;

    float pp = (tid < NROWS) ? ((float)mydeg * ((float)mydeg - 1.0f)) : 0.f;
    float poss = blockReduceSum(pp, red) * 0.5f;

    float m2 = 2.0f * ne;
    float m2s = (m2 > 0.f) ? m2 : 1.0f;
    float macc = 0.f;
    if (tid < NROWS) {
        int ci = comm[tid];
        float di = (float)mydeg;
        #pragma unroll 2
        for (int j = 0; j < NROWS; j++) {
            if (j != tid && comm[j] == ci) {
                float bij = (float)((bits[tid][j >> 5] >> (j & 31)) & 1u);
                macc += bij - di * degf[j] / m2s;
            }
        }
    }
    float modsum = blockReduceSum(macc, red);
    float mod = (m2 > 0.f) ? (modsum / m2s) : 0.f;

    // node5 means
    if (tid < 5) {
        const float* f = g_feat + (size_t)band * 5 * NROWS + tid * NROWS;
        float sm = 0.f;
        for (int r = 0; r < NROWS; r++) sm += f[r];
        feat11[tid] = sm / (float)NROWS;
    }
    if (tid == 0) {
        float n = (float)NROWS;
        sprops[0] = ne;
        sprops[1] = ne / (n * (n - 1.0f) * 0.5f);
        sprops[2] = degsum / n;
        sprops[3] = (poss > 0.f) ? (tri / poss) : 0.f;
        sprops[4] = (n + 2.0f * ne) / (n * (n - 1.0f));
        sprops[5] = mod;
    }
    __syncthreads();
    if (tid < 6) feat11[5 + tid] = sprops[tid];
    __syncthreads();

    if (tid < 32) {
        float acc = b1[tid];
        #pragma unroll
        for (int k = 0; k < 11; k++) acc = fmaf(feat11[k], W1[tid * 11 + k], acc);
        h[tid] = fmaxf(acc, 0.f);
    }
    __syncthreads();
    if (tid < 64) {
        float acc = b2[tid];
        #pragma unroll
        for (int k = 0; k < 32; k++) acc = fmaf(h[k], W2[tid * 32 + k], acc);
        outF[(size_t)band * 64 + tid] = acc;
    }
}

// ---------------- launch ----------------
extern "C" void kernel_launch(void* const* d_in, const int* in_sizes, int n_in,
                              void* d_out, int out_size) {
    const float* wc       = (const float*)d_in[0];
    const int*   community= (const int*)d_in[2];
    const float* W1       = (const float*)d_in[3];
    const float* b1       = (const float*)d_in[4];
    const float* W2       = (const float*)d_in[5];
    const float* b2       = (const float*)d_in[6];

    float* out = (float*)d_out;
    float* outA = out;                                   // 32*5*96*96
    float* outF = out + (size_t)NBANDS * NROWS * NROWS;  // 32*5*64

    dim3 gA(NROWS, NBANDS);
    stats_fft_kernel<<<gA, 256>>>(wc);
    dim3 gC(2, NBANDS);
    corr_kernel<<<gC, 256>>>();
    quantile_kernel<<<NBANDS, 1024>>>();
    finalize_kernel<<<NBANDS, 128>>>(community, W1, b1, W2, b2, outA, outF);
}

// round 3
// speedup vs baseline: 1.6096x; 1.6096x over previous
#include <cuda_runtime.h>
#include <cuda_bf16.h>
#include <math.h>
#include <stdint.h>

#define NBANDS 160
#define NROWS  96
#define TLEN   2048
#define HALF_T 1024
#define NTRIL  4560   // 96*95/2
#define SORTN  8192

// ---------------- scratch (static device globals; no allocation) ----------------
__device__ float  g_xc[(size_t)NBANDS * NROWS * TLEN];    // centered rows (fp32, unnormalized)
__device__ double g_norm2[(size_t)NBANDS * NROWS];        // ||Xc||^2 in fp64
__device__ float  g_C[(size_t)NBANDS * NROWS * NROWS];    // correlation matrices (fp32, correctly rounded)
__device__ float  g_feat[(size_t)NBANDS * 5 * NROWS];     // per-row 5 features
__device__ float  g_thr[NBANDS];

// ---------------- reductions ----------------
__device__ __forceinline__ float blockReduceSum(float val, float* red) {
    __syncthreads();
    int lane = threadIdx.x & 31, wid = threadIdx.x >> 5;
    #pragma unroll
    for (int o = 16; o > 0; o >>= 1) val += __shfl_xor_sync(0xffffffffu, val, o);
    if (lane == 0) red[wid] = val;
    __syncthreads();
    if (wid == 0) {
        int nw = (blockDim.x + 31) >> 5;
        float v = (lane < nw) ? red[lane] : 0.f;
        #pragma unroll
        for (int o = 16; o > 0; o >>= 1) v += __shfl_xor_sync(0xffffffffu, v, o);
        if (lane == 0) red[0] = v;
    }
    __syncthreads();
    return red[0];
}

__device__ __forceinline__ double blockReduceSumD(double val, double* redd) {
    __syncthreads();
    int lane = threadIdx.x & 31, wid = threadIdx.x >> 5;
    #pragma unroll
    for (int o = 16; o > 0; o >>= 1) val += __shfl_xor_sync(0xffffffffu, val, o);
    if (lane == 0) redd[wid] = val;
    __syncthreads();
    if (wid == 0) {
        int nw = (blockDim.x + 31) >> 5;
        double v = (lane < nw) ? redd[lane] : 0.0;
        #pragma unroll
        for (int o = 16; o > 0; o >>= 1) v += __shfl_xor_sync(0xffffffffu, v, o);
        if (lane == 0) redd[0] = v;
    }
    __syncthreads();
    return redd[0];
}

__device__ __forceinline__ float blockReduceMax(float val, float* red) {
    __syncthreads();
    int lane = threadIdx.x & 31, wid = threadIdx.x >> 5;
    #pragma unroll
    for (int o = 16; o > 0; o >>= 1) val = fmaxf(val, __shfl_xor_sync(0xffffffffu, val, o));
    if (lane == 0) red[wid] = val;
    __syncthreads();
    if (wid == 0) {
        int nw = (blockDim.x + 31) >> 5;
        float v = (lane < nw) ? red[lane] : -INFINITY;
        #pragma unroll
        for (int o = 16; o > 0; o >>= 1) v = fmaxf(v, __shfl_xor_sync(0xffffffffu, v, o));
        if (lane == 0) red[0] = v;
    }
    __syncthreads();
    return red[0];
}

// ---------------- kernel 1: per-row stats + center (fp64 mean) + FFT entropy ----------------
// grid (96, 160), block 256
__global__ void stats_fft_kernel(const float* __restrict__ wc) {
    const int row = blockIdx.x;
    const int band = blockIdx.y;
    const int b = band / 5, nb = band % 5;
    const float* __restrict__ x = wc + (((size_t)b * NROWS + row) * 5 + nb) * TLEN;

    __shared__ float re[TLEN];
    __shared__ float im[TLEN];
    __shared__ float twr[HALF_T];
    __shared__ float twi[HALF_T];
    __shared__ float red[32];
    __shared__ double redd[32];

    const int tid = threadIdx.x;

    float v[8];
    double s = 0.0, sq = 0.0;
    float mx = 0.f;
    #pragma unroll
    for (int k = 0; k < 8; k++) {
        float t = x[tid + 256 * k];
        v[k] = t;
        s += (double)t; sq += (double)t * (double)t; mx = fmaxf(mx, fabsf(t));
    }

    // twiddles: tw[k] = exp(-2*pi*i*k/2048)
    for (int k = tid; k < HALF_T; k += 256) {
        float sv, cv;
        sincospif(-(float)k / 1024.0f, &sv, &cv);
        twr[k] = cv; twi[k] = sv;
    }
    // bit-reversed load of original x (FFT is on un-centered X)
    #pragma unroll
    for (int k = 0; k < 8; k++) {
        int idx = tid + 256 * k;
        int r = __brev((unsigned)idx) >> 21;  // 11-bit reverse
        re[r] = v[k];
        im[r] = 0.f;
    }

    double ssum   = blockReduceSumD(s, redd);
    double energy = blockReduceSumD(sq, redd);
    float  maxamp = blockReduceMax(mx, red);
    float  meanf  = (float)(ssum / (double)TLEN);

    // centered rows in fp32 (matches reference's fp32 Xc), norm^2 in fp64
    float cx[8];
    double csq = 0.0;
    #pragma unroll
    for (int k = 0; k < 8; k++) {
        cx[k] = v[k] - meanf;
        csq += (double)cx[k] * (double)cx[k];
    }
    double norm2 = blockReduceSumD(csq, redd);
    float stdf = (float)sqrt(norm2 / (double)(TLEN - 1));

    float* __restrict__ xc = g_xc + ((size_t)band * NROWS + row) * TLEN;
    #pragma unroll
    for (int k = 0; k < 8; k++) xc[tid + 256 * k] = cx[k];
    if (tid == 0) g_norm2[(size_t)band * NROWS + row] = norm2;

    // FFT (DIT radix-2, bit-reversed input, natural output)
    #pragma unroll 1
    for (int st = 1; st <= 11; st++) {
        const int half = 1 << (st - 1);
        __syncthreads();
        #pragma unroll 1
        for (int bfly = tid; bfly < HALF_T; bfly += 256) {
            int j = bfly & (half - 1);
            int grp = bfly >> (st - 1);
            int p0 = (grp << st) + j;
            int p1 = p0 + half;
            int ti = j << (11 - st);
            float wr = twr[ti], wi = twi[ti];
            float r1 = re[p1], i1 = im[p1];
            float vr = r1 * wr - i1 * wi;
            float vi = r1 * wi + i1 * wr;
            float ur = re[p0], ui = im[p0];
            re[p0] = ur + vr; im[p0] = ui + vi;
            re[p1] = ur - vr; im[p1] = ui - vi;
        }
    }
    __syncthreads();

    double psum = 0.0;
    for (int k = tid; k < HALF_T; k += 256) {
        float ps = re[k] * re[k] + im[k] * im[k];
        psum += (double)ps;
    }
    double S = blockReduceSumD(psum, redd);
    double Sd = (S == 0.0) ? 1.0 : S;
    double entp = 0.0;
    for (int k = tid; k < HALF_T; k += 256) {
        float ps = re[k] * re[k] + im[k] * im[k];
        float p = (float)((double)ps / Sd);
        entp += (double)(p * logf(p + 1e-10f));
    }
    double ent = -blockReduceSumD(entp, redd);

    if (tid == 0) {
        float* f = g_feat + (size_t)band * 5 * NROWS;
        f[0 * NROWS + row] = meanf;
        f[1 * NROWS + row] = stdf;
        f[2 * NROWS + row] = (float)energy;
        f[3 * NROWS + row] = maxamp;
        f[4 * NROWS + row] = (float)ent;
    }
}

// ---------------- kernel 2: correlation GEMM C = Xc @ Xc^T / (norm norm^T) per band ----------------
// grid (2, 160): each block does 48 rows x 96 cols. block 256 (16x16), thread tile 3x6.
// fp32 FMA inner loops over K-chunks of 64; chunk sums accumulated into fp64.
__global__ void corr_kernel() {
    const int band = blockIdx.y;
    const int half = blockIdx.x;          // 0 or 1 (rows 0-47 / 48-95)
    __shared__ float st[64][97];          // transposed tile: st[k][row]
    __shared__ double n2s[NROWS];
    const float* __restrict__ Xb = g_xc + (size_t)band * NROWS * TLEN;

    const int tid = threadIdx.x;
    const int tx = tid & 15, ty = tid >> 4;

    if (tid < NROWS) n2s[tid] = g_norm2[(size_t)band * NROWS + tid];

    double accd[3][6];
    #pragma unroll
    for (int u = 0; u < 3; u++)
        #pragma unroll
        for (int w = 0; w < 6; w++) accd[u][w] = 0.0;

    const int rbase = half * 48;

    for (int kt = 0; kt < TLEN; kt += 64) {
        // load 96 rows x 64 k, transposed into smem
        #pragma unroll
        for (int i = tid; i < 1536; i += 256) {
            int r = i >> 4, q = i & 15;
            float4 g = *reinterpret_cast<const float4*>(Xb + (size_t)r * TLEN + kt + q * 4);
            st[q * 4 + 0][r] = g.x;
            st[q * 4 + 1][r] = g.y;
            st[q * 4 + 2][r] = g.z;
            st[q * 4 + 3][r] = g.w;
        }
        __syncthreads();

        float acc[3][6];
        #pragma unroll
        for (int u = 0; u < 3; u++)
            #pragma unroll
            for (int w = 0; w < 6; w++) acc[u][w] = 0.f;

        #pragma unroll 4
        for (int k = 0; k < 64; k++) {
            float a[3], bb[6];
            #pragma unroll
            for (int u = 0; u < 3; u++) a[u]  = st[k][rbase + ty + 16 * u];
            #pragma unroll
            for (int w = 0; w < 6; w++) bb[w] = st[k][tx + 16 * w];
            #pragma unroll
            for (int u = 0; u < 3; u++)
                #pragma unroll
                for (int w = 0; w < 6; w++)
                    acc[u][w] = fmaf(a[u], bb[w], acc[u][w]);
        }
        __syncthreads();

        #pragma unroll
        for (int u = 0; u < 3; u++)
            #pragma unroll
            for (int w = 0; w < 6; w++) accd[u][w] += (double)acc[u][w];
    }

    float* __restrict__ Cb = g_C + (size_t)band * NROWS * NROWS;
    #pragma unroll
    for (int u = 0; u < 3; u++) {
        int r = rbase + ty + 16 * u;
        double ni = sqrt(n2s[r]);
        if (ni == 0.0) ni = 1.0;
        #pragma unroll
        for (int w = 0; w < 6; w++) {
            int c = tx + 16 * w;
            double nj = sqrt(n2s[c]);
            if (nj == 0.0) nj = 1.0;
            double val = accd[u][w] / (ni * nj);
            Cb[r * NROWS + c] = (r == c) ? 0.f : (float)val;
        }
    }
}

// ---------------- kernel 3: exact quantile via bitonic sort ----------------
// grid 160, block 1024
__global__ void quantile_kernel() {
    __shared__ float s[SORTN];
    const int band = blockIdx.x;
    const int tid = threadIdx.x;
    const float* __restrict__ Cb = g_C + (size_t)band * NROWS * NROWS;

    for (int i = tid; i < SORTN; i += 1024) s[i] = INFINITY;
    __syncthreads();
    for (int idx = tid; idx < NROWS * NROWS; idx += 1024) {
        int i = idx / NROWS, j = idx - i * NROWS;
        if (j < i) s[i * (i - 1) / 2 + j] = fabsf(Cb[idx]);
    }

    for (int k = 2; k <= SORTN; k <<= 1) {
        for (int j = k >> 1; j > 0; j >>= 1) {
            __syncthreads();
            #pragma unroll 1
            for (int i = tid; i < SORTN; i += 1024) {
                int ixj = i ^ j;
                if (ixj > i) {
                    float a = s[i], b = s[ixj];
                    bool up = ((i & k) == 0);
                    if ((a > b) == up) { s[i] = b; s[ixj] = a; }
                }
            }
        }
    }
    __syncthreads();
    if (tid == 0) {
        // q = 0.8, N = 4560 -> pos = 0.8*(N-1) = 3647.2
        double pos = 0.8 * (double)(NTRIL - 1);
        int lo = (int)pos;
        double fr = pos - (double)lo;
        g_thr[band] = (float)((double)s[lo] + fr * ((double)s[lo + 1] - (double)s[lo]));
    }
}

// ---------------- kernel 4: mask + graph props + MLP ----------------
// grid 160, block 128
__global__ void finalize_kernel(const int* __restrict__ community,
                                const float* __restrict__ W1, const float* __restrict__ b1,
                                const float* __restrict__ W2, const float* __restrict__ b2,
                                float* __restrict__ outA, float* __restrict__ outF) {
    const int band = blockIdx.x;
    const int tid = threadIdx.x;

    __shared__ unsigned bits[NROWS][3];
    __shared__ float degf[NROWS];
    __shared__ int comm[NROWS];
    __shared__ float red[32];
    __shared__ float feat11[11];
    __shared__ float h[32];
    __shared__ float sprops[6];

    const float thr = g_thr[band];
    const float* __restrict__ Cb = g_C + (size_t)band * NROWS * NROWS;
    float* __restrict__ Ao = outA + (size_t)band * NROWS * NROWS;

    if (tid < NROWS) comm[tid] = community[tid];

    int mydeg = 0;
    if (tid < NROWS) {
        unsigned b0 = 0, b1w = 0, b2w = 0;
        const float* crow = Cb + tid * NROWS;
        float* arow = Ao + tid * NROWS;
        #pragma unroll 4
        for (int j = 0; j < NROWS; j++) {
            float c = crow[j];
            bool keep = (fabsf(c) >= thr) && (j != tid);
            arow[j] = keep ? c : 0.f;
            if (keep) {
                mydeg++;
                if (j < 32) b0 |= 1u << j;
                else if (j < 64) b1w |= 1u << (j - 32);
                else b2w |= 1u << (j - 64);
            }
        }
        bits[tid][0] = b0; bits[tid][1] = b1w; bits[tid][2] = b2w;
        degf[tid] = (float)mydeg;
    }
    __syncthreads();

    float degsum = blockReduceSum(tid < NROWS ? (float)mydeg : 0.f, red);
    float ne = 0.5f * degsum;

    // triangles: sum over ordered (i,j) edges of |N(i) ∩ N(j)| = 6*tri
    float cnt = 0.f;
    if (tid < NROWS) {
        unsigned r0 = bits[tid][0], r1 = bits[tid][1], r2 = bits[tid][2];
        int c6 = 0;
        #pragma unroll 1
        for (int w = 0; w < 3; w++) {
            unsigned mw = bits[tid][w];
            while (mw) {
                int j = __ffs(mw) - 1 + 32 * w;
                mw &= mw - 1;
                c6 += __popc(r0 & bits[j][0]) + __popc(r1 & bits[j][1]) + __popc(r2 & bits[j][2]);
            }
        }
        cnt = (float)c6;
    }
    float tri6 = blockReduceSum(cnt, red);
    float tri = tri6 / 6.0f;

    float pp = (tid < NROWS) ? ((float)mydeg * ((float)mydeg - 1.0f)) : 0.f;
    float poss = blockReduceSum(pp, red) * 0.5f;

    float m2 = 2.0f * ne;
    float m2s = (m2 > 0.f) ? m2 : 1.0f;
    float macc = 0.f;
    if (tid < NROWS) {
        int ci = comm[tid];
        float di = (float)mydeg;
        #pragma unroll 2
        for (int j = 0; j < NROWS; j++) {
            if (j != tid && comm[j] == ci) {
                float bij = (float)((bits[tid][j >> 5] >> (j & 31)) & 1u);
                macc += bij - di * degf[j] / m2s;
            }
        }
    }
    float modsum = blockReduceSum(macc, red);
    float mod = (m2 > 0.f) ? (modsum / m2s) : 0.f;

    // node5 means
    if (tid < 5) {
        const float* f = g_feat + (size_t)band * 5 * NROWS + tid * NROWS;
        float sm = 0.f;
        for (int r = 0; r < NROWS; r++) sm += f[r];
        feat11[tid] = sm / (float)NROWS;
    }
    if (tid == 0) {
        float n = (float)NROWS;
        sprops[0] = ne;
        sprops[1] = ne / (n * (n - 1.0f) * 0.5f);
        sprops[2] = degsum / n;
        sprops[3] = (poss > 0.f) ? (tri / poss) : 0.f;
        sprops[4] = (n + 2.0f * ne) / (n * (n - 1.0f));
        sprops[5] = mod;
    }
    __syncthreads();
    if (tid < 6) feat11[5 + tid] = sprops[tid];
    __syncthreads();

    if (tid < 32) {
        float acc = b1[tid];
        #pragma unroll
        for (int k = 0; k < 11; k++) acc = fmaf(feat11[k], W1[tid * 11 + k], acc);
        h[tid] = fmaxf(acc, 0.f);
    }
    __syncthreads();
    if (tid < 64) {
        float acc = b2[tid];
        #pragma unroll
        for (int k = 0; k < 32; k++) acc = fmaf(h[k], W2[tid * 32 + k], acc);
        outF[(size_t)band * 64 + tid] = acc;
    }
}

// ---------------- launch ----------------
extern "C" void kernel_launch(void* const* d_in, const int* in_sizes, int n_in,
                              void* d_out, int out_size) {
    const float* wc       = (const float*)d_in[0];
    const int*   community= (const int*)d_in[2];
    const float* W1       = (const float*)d_in[3];
    const float* b1       = (const float*)d_in[4];
    const float* W2       = (const float*)d_in[5];
    const float* b2       = (const float*)d_in[6];

    float* out = (float*)d_out;
    float* outA = out;                                   // 32*5*96*96
    float* outF = out + (size_t)NBANDS * NROWS * NROWS;  // 32*5*64

    dim3 gA(NROWS, NBANDS);
    stats_fft_kernel<<<gA, 256>>>(wc);
    dim3 gC(2, NBANDS);
    corr_kernel<<<gC, 256>>>();
    quantile_kernel<<<NBANDS, 1024>>>();
    finalize_kernel<<<NBANDS, 128>>>(community, W1, b1, W2, b2, outA, outF);
}

// round 4
// speedup vs baseline: 1.6153x; 1.0035x over previous
#include <cuda_runtime.h>
#include <cuda_bf16.h>
#include <math.h>
#include <stdint.h>

#define NBANDS 160
#define NROWS  96
#define TLEN   2048
#define HALF_T 1024
#define NTRIL  4560   // 96*95/2
#define SORTN  8192

// ---------------- scratch (static device globals; no allocation) ----------------
__device__ float  g_xc[(size_t)NBANDS * NROWS * TLEN];    // centered rows (fp32, unnormalized)
__device__ double g_norm2[(size_t)NBANDS * NROWS];        // ||Xc||^2 in fp64
__device__ float  g_C[(size_t)NBANDS * NROWS * NROWS];    // correlation matrices (fp32, correctly rounded)
__device__ float  g_feat[(size_t)NBANDS * 5 * NROWS];     // per-row 5 features
__device__ float  g_thr[NBANDS];

// ---------------- reductions ----------------
__device__ __forceinline__ float blockReduceSum(float val, float* red) {
    __syncthreads();
    int lane = threadIdx.x & 31, wid = threadIdx.x >> 5;
    #pragma unroll
    for (int o = 16; o > 0; o >>= 1) val += __shfl_xor_sync(0xffffffffu, val, o);
    if (lane == 0) red[wid] = val;
    __syncthreads();
    if (wid == 0) {
        int nw = (blockDim.x + 31) >> 5;
        float v = (lane < nw) ? red[lane] : 0.f;
        #pragma unroll
        for (int o = 16; o > 0; o >>= 1) v += __shfl_xor_sync(0xffffffffu, v, o);
        if (lane == 0) red[0] = v;
    }
    __syncthreads();
    return red[0];
}

__device__ __forceinline__ double blockReduceSumD(double val, double* redd) {
    __syncthreads();
    int lane = threadIdx.x & 31, wid = threadIdx.x >> 5;
    #pragma unroll
    for (int o = 16; o > 0; o >>= 1) val += __shfl_xor_sync(0xffffffffu, val, o);
    if (lane == 0) redd[wid] = val;
    __syncthreads();
    if (wid == 0) {
        int nw = (blockDim.x + 31) >> 5;
        double v = (lane < nw) ? redd[lane] : 0.0;
        #pragma unroll
        for (int o = 16; o > 0; o >>= 1) v += __shfl_xor_sync(0xffffffffu, v, o);
        if (lane == 0) redd[0] = v;
    }
    __syncthreads();
    return redd[0];
}

__device__ __forceinline__ float blockReduceMax(float val, float* red) {
    __syncthreads();
    int lane = threadIdx.x & 31, wid = threadIdx.x >> 5;
    #pragma unroll
    for (int o = 16; o > 0; o >>= 1) val = fmaxf(val, __shfl_xor_sync(0xffffffffu, val, o));
    if (lane == 0) red[wid] = val;
    __syncthreads();
    if (wid == 0) {
        int nw = (blockDim.x + 31) >> 5;
        float v = (lane < nw) ? red[lane] : -INFINITY;
        #pragma unroll
        for (int o = 16; o > 0; o >>= 1) v = fmaxf(v, __shfl_xor_sync(0xffffffffu, v, o));
        if (lane == 0) red[0] = v;
    }
    __syncthreads();
    return red[0];
}

// ---------------- kernel 1: per-row stats + center (fp64 mean) + FFT entropy ----------------
// grid (96, 160), block 256
__global__ void stats_fft_kernel(const float* __restrict__ wc) {
    const int row = blockIdx.x;
    const int band = blockIdx.y;
    const int b = band / 5, nb = band % 5;
    const float* __restrict__ x = wc + (((size_t)b * NROWS + row) * 5 + nb) * TLEN;

    __shared__ float re[TLEN];
    __shared__ float im[TLEN];
    __shared__ float twr[HALF_T];
    __shared__ float twi[HALF_T];
    __shared__ float red[32];
    __shared__ double redd[32];

    const int tid = threadIdx.x;

    float v[8];
    double s = 0.0, sq = 0.0;
    float mx = 0.f;
    #pragma unroll
    for (int k = 0; k < 8; k++) {
        float t = x[tid + 256 * k];
        v[k] = t;
        s += (double)t; sq += (double)t * (double)t; mx = fmaxf(mx, fabsf(t));
    }

    // twiddles: tw[k] = exp(-2*pi*i*k/2048)
    for (int k = tid; k < HALF_T; k += 256) {
        float sv, cv;
        sincospif(-(float)k / 1024.0f, &sv, &cv);
        twr[k] = cv; twi[k] = sv;
    }
    // bit-reversed load of original x (FFT is on un-centered X)
    #pragma unroll
    for (int k = 0; k < 8; k++) {
        int idx = tid + 256 * k;
        int r = __brev((unsigned)idx) >> 21;  // 11-bit reverse
        re[r] = v[k];
        im[r] = 0.f;
    }

    double ssum   = blockReduceSumD(s, redd);
    double energy = blockReduceSumD(sq, redd);
    float  maxamp = blockReduceMax(mx, red);
    float  meanf  = (float)(ssum / (double)TLEN);

    // centered rows in fp32 (matches reference's fp32 Xc), norm^2 in fp64
    float cx[8];
    double csq = 0.0;
    #pragma unroll
    for (int k = 0; k < 8; k++) {
        cx[k] = v[k] - meanf;
        csq += (double)cx[k] * (double)cx[k];
    }
    double norm2 = blockReduceSumD(csq, redd);
    float stdf = (float)sqrt(norm2 / (double)(TLEN - 1));

    float* __restrict__ xc = g_xc + ((size_t)band * NROWS + row) * TLEN;
    #pragma unroll
    for (int k = 0; k < 8; k++) xc[tid + 256 * k] = cx[k];
    if (tid == 0) g_norm2[(size_t)band * NROWS + row] = norm2;

    // FFT (DIT radix-2, bit-reversed input, natural output)
    #pragma unroll 1
    for (int st = 1; st <= 11; st++) {
        const int half = 1 << (st - 1);
        __syncthreads();
        #pragma unroll 1
        for (int bfly = tid; bfly < HALF_T; bfly += 256) {
            int j = bfly & (half - 1);
            int grp = bfly >> (st - 1);
            int p0 = (grp << st) + j;
            int p1 = p0 + half;
            int ti = j << (11 - st);
            float wr = twr[ti], wi = twi[ti];
            float r1 = re[p1], i1 = im[p1];
            float vr = r1 * wr - i1 * wi;
            float vi = r1 * wi + i1 * wr;
            float ur = re[p0], ui = im[p0];
            re[p0] = ur + vr; im[p0] = ui + vi;
            re[p1] = ur - vr; im[p1] = ui - vi;
        }
    }
    __syncthreads();

    double psum = 0.0;
    for (int k = tid; k < HALF_T; k += 256) {
        float ps = re[k] * re[k] + im[k] * im[k];
        psum += (double)ps;
    }
    double S = blockReduceSumD(psum, redd);
    double Sd = (S == 0.0) ? 1.0 : S;
    double entp = 0.0;
    for (int k = tid; k < HALF_T; k += 256) {
        float ps = re[k] * re[k] + im[k] * im[k];
        float p = (float)((double)ps / Sd);
        entp += (double)(p * logf(p + 1e-10f));
    }
    double ent = -blockReduceSumD(entp, redd);

    if (tid == 0) {
        float* f = g_feat + (size_t)band * 5 * NROWS;
        f[0 * NROWS + row] = meanf;
        f[1 * NROWS + row] = stdf;
        f[2 * NROWS + row] = (float)energy;
        f[3 * NROWS + row] = maxamp;
        f[4 * NROWS + row] = (float)ent;
    }
}

// ---------------- kernel 2: correlation GEMM C = Xc @ Xc^T / (norm norm^T) per band ----------------
// grid (2, 160): each block does 48 rows x 96 cols. block 256 (16x16), thread tile 3x6.
// fp32 FMA inner loops over K-chunks of 64; chunk sums accumulated into fp64.
__global__ void corr_kernel() {
    const int band = blockIdx.y;
    const int half = blockIdx.x;          // 0 or 1 (rows 0-47 / 48-95)
    __shared__ float st[64][97];          // transposed tile: st[k][row]
    __shared__ double n2s[NROWS];
    const float* __restrict__ Xb = g_xc + (size_t)band * NROWS * TLEN;

    const int tid = threadIdx.x;
    const int tx = tid & 15, ty = tid >> 4;

    if (tid < NROWS) n2s[tid] = g_norm2[(size_t)band * NROWS + tid];

    double accd[3][6];
    #pragma unroll
    for (int u = 0; u < 3; u++)
        #pragma unroll
        for (int w = 0; w < 6; w++) accd[u][w] = 0.0;

    const int rbase = half * 48;

    for (int kt = 0; kt < TLEN; kt += 64) {
        // load 96 rows x 64 k, transposed into smem
        #pragma unroll
        for (int i = tid; i < 1536; i += 256) {
            int r = i >> 4, q = i & 15;
            float4 g = *reinterpret_cast<const float4*>(Xb + (size_t)r * TLEN + kt + q * 4);
            st[q * 4 + 0][r] = g.x;
            st[q * 4 + 1][r] = g.y;
            st[q * 4 + 2][r] = g.z;
            st[q * 4 + 3][r] = g.w;
        }
        __syncthreads();

        float acc[3][6];
        #pragma unroll
        for (int u = 0; u < 3; u++)
            #pragma unroll
            for (int w = 0; w < 6; w++) acc[u][w] = 0.f;

        #pragma unroll 4
        for (int k = 0; k < 64; k++) {
            float a[3], bb[6];
            #pragma unroll
            for (int u = 0; u < 3; u++) a[u]  = st[k][rbase + ty + 16 * u];
            #pragma unroll
            for (int w = 0; w < 6; w++) bb[w] = st[k][tx + 16 * w];
            #pragma unroll
            for (int u = 0; u < 3; u++)
                #pragma unroll
                for (int w = 0; w < 6; w++)
                    acc[u][w] = fmaf(a[u], bb[w], acc[u][w]);
        }
        __syncthreads();

        #pragma unroll
        for (int u = 0; u < 3; u++)
            #pragma unroll
            for (int w = 0; w < 6; w++) accd[u][w] += (double)acc[u][w];
    }

    float* __restrict__ Cb = g_C + (size_t)band * NROWS * NROWS;
    #pragma unroll
    for (int u = 0; u < 3; u++) {
        int r = rbase + ty + 16 * u;
        double ni = sqrt(n2s[r]);
        if (ni == 0.0) ni = 1.0;
        #pragma unroll
        for (int w = 0; w < 6; w++) {
            int c = tx + 16 * w;
            double nj = sqrt(n2s[c]);
            if (nj == 0.0) nj = 1.0;
            double val = accd[u][w] / (ni * nj);
            Cb[r * NROWS + c] = (r == c) ? 0.f : (float)val;
        }
    }
}

// ---------------- kernel 3: exact quantile via bitonic sort ----------------
// grid 160, block 1024
__global__ void quantile_kernel() {
    __shared__ float s[SORTN];
    const int band = blockIdx.x;
    const int tid = threadIdx.x;
    const float* __restrict__ Cb = g_C + (size_t)band * NROWS * NROWS;

    for (int i = tid; i < SORTN; i += 1024) s[i] = INFINITY;
    __syncthreads();
    for (int idx = tid; idx < NROWS * NROWS; idx += 1024) {
        int i = idx / NROWS, j = idx - i * NROWS;
        if (j < i) s[i * (i - 1) / 2 + j] = fabsf(Cb[idx]);
    }

    for (int k = 2; k <= SORTN; k <<= 1) {
        for (int j = k >> 1; j > 0; j >>= 1) {
            __syncthreads();
            #pragma unroll 1
            for (int i = tid; i < SORTN; i += 1024) {
                int ixj = i ^ j;
                if (ixj > i) {
                    float a = s[i], b = s[ixj];
                    bool up = ((i & k) == 0);
                    if ((a > b) == up) { s[i] = b; s[ixj] = a; }
                }
            }
        }
    }
    __syncthreads();
    if (tid == 0) {
        // q = 0.8, N = 4560 -> pos = 0.8*(N-1) = 3647.2
        double pos = 0.8 * (double)(NTRIL - 1);
        int lo = (int)pos;
        double fr = pos - (double)lo;
        g_thr[band] = (float)((double)s[lo] + fr * ((double)s[lo + 1] - (double)s[lo]));
    }
}

// ---------------- kernel 4: mask + graph props + MLP ----------------
// grid 160, block 128
__global__ void finalize_kernel(const int* __restrict__ community,
                                const float* __restrict__ W1, const float* __restrict__ b1,
                                const float* __restrict__ W2, const float* __restrict__ b2,
                                float* __restrict__ outA, float* __restrict__ outF) {
    const int band = blockIdx.x;
    const int tid = threadIdx.x;

    __shared__ unsigned bits[NROWS][3];
    __shared__ float degf[NROWS];
    __shared__ int comm[NROWS];
    __shared__ float red[32];
    __shared__ float feat11[11];
    __shared__ float h[32];
    __shared__ float sprops[6];

    const float thr = g_thr[band];
    const float* __restrict__ Cb = g_C + (size_t)band * NROWS * NROWS;
    float* __restrict__ Ao = outA + (size_t)band * NROWS * NROWS;

    if (tid < NROWS) comm[tid] = community[tid];

    int mydeg = 0;
    if (tid < NROWS) {
        unsigned b0 = 0, b1w = 0, b2w = 0;
        const float* crow = Cb + tid * NROWS;
        float* arow = Ao + tid * NROWS;
        #pragma unroll 4
        for (int j = 0; j < NROWS; j++) {
            float c = crow[j];
            bool keep = (fabsf(c) >= thr) && (j != tid);
            arow[j] = keep ? c : 0.f;
            if (keep) {
                mydeg++;
                if (j < 32) b0 |= 1u << j;
                else if (j < 64) b1w |= 1u << (j - 32);
                else b2w |= 1u << (j - 64);
            }
        }
        bits[tid][0] = b0; bits[tid][1] = b1w; bits[tid][2] = b2w;
        degf[tid] = (float)mydeg;
    }
    __syncthreads();

    float degsum = blockReduceSum(tid < NROWS ? (float)mydeg : 0.f, red);
    float ne = 0.5f * degsum;

    // triangles: sum over ordered (i,j) edges of |N(i) ∩ N(j)| = 6*tri
    float cnt = 0.f;
    if (tid < NROWS) {
        unsigned r0 = bits[tid][0], r1 = bits[tid][1], r2 = bits[tid][2];
        int c6 = 0;
        #pragma unroll 1
        for (int w = 0; w < 3; w++) {
            unsigned mw = bits[tid][w];
            while (mw) {
                int j = __ffs(mw) - 1 + 32 * w;
                mw &= mw - 1;
                c6 += __popc(r0 & bits[j][0]) + __popc(r1 & bits[j][1]) + __popc(r2 & bits[j][2]);
            }
        }
        cnt = (float)c6;
    }
    float tri6 = blockReduceSum(cnt, red);
    float tri = tri6 / 6.0f;

    float pp = (tid < NROWS) ? ((float)mydeg * ((float)mydeg - 1.0f)) : 0.f;
    float poss = blockReduceSum(pp, red) * 0.5f;

    float m2 = 2.0f * ne;
    float m2s = (m2 > 0.f) ? m2 : 1.0f;
    float macc = 0.f;
    if (tid < NROWS) {
        int ci = comm[tid];
        float di = (float)mydeg;
        #pragma unroll 2
        for (int j = 0; j < NROWS; j++) {
            if (j != tid && comm[j] == ci) {
                float bij = (float)((bits[tid][j >> 5] >> (j & 31)) & 1u);
                macc += bij - di * degf[j] / m2s;
            }
        }
    }
    float modsum = blockReduceSum(macc, red);
    float mod = (m2 > 0.f) ? (modsum / m2s) : 0.f;

    // node5 means
    if (tid < 5) {
        const float* f = g_feat + (size_t)band * 5 * NROWS + tid * NROWS;
        float sm = 0.f;
        for (int r = 0; r < NROWS; r++) sm += f[r];
        feat11[tid] = sm / (float)NROWS;
    }
    if (tid == 0) {
        float n = (float)NROWS;
        sprops[0] = ne;
        sprops[1] = ne / (n * (n - 1.0f) * 0.5f);
        sprops[2] = degsum / n;
        sprops[3] = (poss > 0.f) ? (tri / poss) : 0.f;
        sprops[4] = (n + 2.0f * ne) / (n * (n - 1.0f));
        sprops[5] = mod;
    }
    __syncthreads();
    if (tid < 6) feat11[5 + tid] = sprops[tid];
    __syncthreads();

    if (tid < 32) {
        float acc = b1[tid];
        #pragma unroll
        for (int k = 0; k < 11; k++) acc = fmaf(feat11[k], W1[tid * 11 + k], acc);
        h[tid] = fmaxf(acc, 0.f);
    }
    __syncthreads();
    if (tid < 64) {
        float acc = b2[tid];
        #pragma unroll
        for (int k = 0; k < 32; k++) acc = fmaf(h[k], W2[tid * 32 + k], acc);
        outF[(size_t)band * 64 + tid] = acc;
    }
}

// ---------------- launch ----------------
extern "C" void kernel_launch(void* const* d_in, const int* in_sizes, int n_in,
                              void* d_out, int out_size) {
    const float* wc       = (const float*)d_in[0];
    const int*   community= (const int*)d_in[2];
    const float* W1       = (const float*)d_in[3];
    const float* b1       = (const float*)d_in[4];
    const float* W2       = (const float*)d_in[5];
    const float* b2       = (const float*)d_in[6];

    float* out = (float*)d_out;
    float* outA = out;                                   // 32*5*96*96
    float* outF = out + (size_t)NBANDS * NROWS * NROWS;  // 32*5*64

    dim3 gA(NROWS, NBANDS);
    stats_fft_kernel<<<gA, 256>>>(wc);
    dim3 gC(2, NBANDS);
    corr_kernel<<<gC, 256>>>();
    quantile_kernel<<<NBANDS, 1024>>>();
    finalize_kernel<<<NBANDS, 128>>>(community, W1, b1, W2, b2, outA, outF);
}